// round 16
// baseline (speedup 1.0000x reference)
#include <cuda_runtime.h>

// Quan2d, round 16: R15 body (shared row gates + shared wire-3 col gate +
// eliminated L2 wire-3) with occupancy forced to 7 CTAs/SM (36-reg cap).
// Constant live ranges split (reload from smem at use sites) so ptxas can
// rematerialize instead of spilling.
//
// Math: all gates tangent form (RY = c*[[1,-t],[t,1]]; uniform scalars
// cancel). <Z_w> = 2*S_w/n - 1. L2 wire-3 gate eliminated:
// S3 = sum (lo - t3*hi)^2 with j3 = 1/(1+t3^2) correction.
// CNOT ring perm h: {0,13,3,14,6,11,5,8,12,1,15,2,10,7,9,4}.

__host__ __device__ constexpr int permIdx(int s) {
    int b0 = (s >> 3) & 1, b1 = (s >> 2) & 1, b2 = (s >> 1) & 1, b3 = s & 1;
    int h0 = b0 ^ b3, h1 = b0 ^ b1 ^ b3, h2 = b1 ^ b2, h3 = b2 ^ b3;
    return (h0 << 3) | (h1 << 2) | (h2 << 1) | h3;
}

__device__ __forceinline__ float frcp_approx(float v) {
    float r; asm("rcp.approx.f32 %0, %1;" : "=f"(r) : "f"(v)); return r;
}

// smem constant slots:
// [0..3]  L1 tangents t0..t3
// [4..6]  L2 tangents wires 0..2
// [7]     L2 wire-3 tangent t3L2
// [8]     j3 = 1/(1+t3L2^2)
__device__ __forceinline__ float4 run_patch(const float* __restrict__ T, int off,
                                            const float* __restrict__ sh) {
    // L1 wire-2 gate (bit value 2): pairs (c0,c2),(c1,c3) per row.
    const float t2 = sh[2];
    float b[16];
    #pragma unroll
    for (int r = 0; r < 4; r++) {
        const float x0 = T[6 * r + off + 0], x1 = T[6 * r + off + 1];
        const float x2 = T[6 * r + off + 2], x3 = T[6 * r + off + 3];
        b[4 * r + 0] = fmaf(-t2, x2, x0);
        b[4 * r + 2] = fmaf( t2, x0, x2);
        b[4 * r + 1] = fmaf(-t2, x3, x1);
        b[4 * r + 3] = fmaf( t2, x1, x3);
    }

    // CNOT ring permutation (register renaming)
    float t[16];
    #pragma unroll
    for (int s = 0; s < 16; s++) t[s] = b[permIdx(s)];

    // L2 wires 0,1,2 (bits 8,4,2); wire 3 eliminated.
    #pragma unroll
    for (int g = 0; g < 3; g++) {
        const float tg = sh[4 + g];          // fresh LDS: short const live range
        const int BIT = 8 >> g;
        #pragma unroll
        for (int lo = 0; lo < 16; lo++) {
            if (lo & BIT) continue;
            const float xx = t[lo], yy = t[lo | BIT];
            t[lo]       = fmaf(-tg, yy, xx);
            t[lo | BIT] = fmaf( tg, xx, yy);
        }
    }

    // bit0-pair sums (uniform (1+t3^2) factor cancels for w=0,1,2)
    float s1[8];
    #pragma unroll
    for (int k = 0; k < 8; k++)
        s1[k] = fmaf(t[2 * k + 1], t[2 * k + 1], t[2 * k] * t[2 * k]);

    float s2[4];
    #pragma unroll
    for (int k = 0; k < 4; k++) s2[k] = s1[2 * k] + s1[2 * k + 1];
    const float s3a = s2[0] + s2[1];
    const float s3b = s2[2] + s2[3];
    const float n   = s3a + s3b;

    const float S0 = s3a;
    const float S1 = s2[0] + s2[2];
    const float S2 = (s1[0] + s1[2]) + (s1[4] + s1[6]);

    // wire 3: lows of the eliminated gate, d_k = lo - t3*hi
    const float t3L2 = sh[7];
    float d0 = fmaf(-t3L2, t[1], t[0]);
    float S3 = d0 * d0;
    #pragma unroll
    for (int k = 1; k < 8; k++) {
        const float dk = fmaf(-t3L2, t[2 * k + 1], t[2 * k]);
        S3 = fmaf(dk, dk, S3);
    }

    const float r2  = 2.0f * frcp_approx(n);
    const float r2j = r2 * sh[8];
    return make_float4(fmaf(S0, r2, -1.0f), fmaf(S1, r2, -1.0f),
                       fmaf(S2, r2, -1.0f), fmaf(S3, r2j, -1.0f));
}

__global__ __launch_bounds__(256, 7)
void quan2d_kernel(const float* __restrict__ x,
                   const float* __restrict__ w8,
                   float* __restrict__ out)
{
    __shared__ float sh[9];
    const int tid = threadIdx.x;
    if (tid < 8) {
        const float tg = __tanf(0.5f * w8[tid]);
        sh[tid] = tg;
        if (tid == 7) sh[8] = frcp_approx(fmaf(tg, tg, 1.0f));
    }
    __syncthreads();

    const int b  = blockIdx.x * 2 + (tid >> 7);   // image
    const int t7 = tid & 127;
    const int pr = t7 >> 3;                        // patch row 0..15
    const int k  = t7 & 7;                         // pair idx; patches pc=2k,2k+1
    const float* img = x + (size_t)b * 1024;

    // --- load 4x6 tile: rows 2pr..2pr+3, cols 4k..4k+5 (zero-pad b/r) ---
    const bool pA = (pr < 15);
    const bool pB = (k < 7);
    float T[24];   // T[6*r + c]
    #pragma unroll
    for (int i = 0; i < 4; i++) {
        const float* base = img + (2 * pr + i) * 32 + 4 * k;
        const bool rok = (i < 2) || pA;
        float4 F = rok ? __ldg((const float4*)base)
                       : make_float4(0.f, 0.f, 0.f, 0.f);
        float2 G = (rok && pB) ? __ldg((const float2*)(base + 4))
                               : make_float2(0.f, 0.f);
        T[6 * i + 0] = F.x; T[6 * i + 1] = F.y;
        T[6 * i + 2] = F.z; T[6 * i + 3] = F.w;
        T[6 * i + 4] = G.x; T[6 * i + 5] = G.y;
    }

    // --- shared L1 row gates (wires 0,1) on all 6 tile columns ---
    {
        const float t0 = sh[0], t1 = sh[1];
        #pragma unroll
        for (int c = 0; c < 6; c++) {
            const float x0 = T[c], x1 = T[6 + c], x2 = T[12 + c], x3 = T[18 + c];
            const float y0 = fmaf(-t0, x2, x0);        // wire 0: (r0,r2),(r1,r3)
            const float y2 = fmaf( t0, x0, x2);
            const float y1 = fmaf(-t0, x3, x1);
            const float y3 = fmaf( t0, x1, x3);
            T[c]      = fmaf(-t1, y1, y0);             // wire 1: (r0,r1),(r2,r3)
            T[6 + c]  = fmaf( t1, y0, y1);
            T[12 + c] = fmaf(-t1, y3, y2);
            T[18 + c] = fmaf( t1, y2, y3);
        }
    }

    // --- shared L1 wire-3 col gate: pairs (0,1),(2,3),(4,5) per row ---
    {
        const float t3 = sh[3];
        #pragma unroll
        for (int r = 0; r < 4; r++) {
            #pragma unroll
            for (int p = 0; p < 3; p++) {
                const float lo = T[6 * r + 2 * p], hi = T[6 * r + 2 * p + 1];
                T[6 * r + 2 * p]     = fmaf(-t3, hi, lo);
                T[6 * r + 2 * p + 1] = fmaf( t3, lo, hi);
            }
        }
    }

    float4* op = (float4*)out + (size_t)b * 256 + pr * 16 + 2 * k;
    op[0] = run_patch(T, 0, sh);
    op[1] = run_patch(T, 2, sh);
}

extern "C" void kernel_launch(void* const* d_in, const int* in_sizes, int n_in,
                              void* d_out, int out_size)
{
    const float* x = (const float*)d_in[0];   // [B,1,32,32] fp32
    const float* w = (const float*)d_in[1];   // [1,8] fp32
    const int B = in_sizes[0] / 1024;
    quan2d_kernel<<<B / 2, 256>>>(x, w, (float*)d_out);
}

// round 17
// speedup vs baseline: 1.2100x; 1.2100x over previous
#include <cuda_runtime.h>

// Quan2d, round 17: R15 math (shared L1 row gates + shared wire-3 col gate,
// L2 wire-3 folded into reduction) + load-path instruction hygiene:
// pre-zeroed tile, guarded predicated loads (no ternary merge selects),
// lean addressing.
//
// Math: tangent-form RY (uniform cos factors cancel), <Z_w> = 2*S_w/n - 1;
// L2 wire-3 eliminated: S3 = sum(lo - t3*hi)^2, j3 = 1/(1+t3^2) correction.
// CNOT ring perm h: {0,13,3,14,6,11,5,8,12,1,15,2,10,7,9,4}.

__host__ __device__ constexpr int permIdx(int s) {
    int b0 = (s >> 3) & 1, b1 = (s >> 2) & 1, b2 = (s >> 1) & 1, b3 = s & 1;
    int h0 = b0 ^ b3, h1 = b0 ^ b1 ^ b3, h2 = b1 ^ b2, h3 = b2 ^ b3;
    return (h0 << 3) | (h1 << 2) | (h2 << 1) | h3;
}

__device__ __forceinline__ float frcp_approx(float v) {
    float r; asm("rcp.approx.f32 %0, %1;" : "=f"(r) : "f"(v)); return r;
}

__device__ __forceinline__ float4 run_patch(const float* __restrict__ T, int off,
                                            const float* __restrict__ ct,
                                            float t3L2, float j3) {
    // L1 wire-2 gate (bit value 2): pairs (c0,c2),(c1,c3) per row.
    const float t2 = ct[2];
    float b[16];
    #pragma unroll
    for (int r = 0; r < 4; r++) {
        const float x0 = T[6 * r + off + 0], x1 = T[6 * r + off + 1];
        const float x2 = T[6 * r + off + 2], x3 = T[6 * r + off + 3];
        b[4 * r + 0] = fmaf(-t2, x2, x0);
        b[4 * r + 2] = fmaf( t2, x0, x2);
        b[4 * r + 1] = fmaf(-t2, x3, x1);
        b[4 * r + 3] = fmaf( t2, x1, x3);
    }

    // CNOT ring permutation (register renaming)
    float t[16];
    #pragma unroll
    for (int s = 0; s < 16; s++) t[s] = b[permIdx(s)];

    // L2 wires 0,1,2 (bits 8,4,2); wire 3 eliminated.
    #pragma unroll
    for (int g = 0; g < 3; g++) {
        const float tg = ct[4 + g];
        const int BIT = 8 >> g;
        #pragma unroll
        for (int lo = 0; lo < 16; lo++) {
            if (lo & BIT) continue;
            const float xx = t[lo], yy = t[lo | BIT];
            t[lo]       = fmaf(-tg, yy, xx);
            t[lo | BIT] = fmaf( tg, xx, yy);
        }
    }

    // bit0-pair sums (uniform (1+t3^2) factor cancels for w=0,1,2)
    float s1[8];
    #pragma unroll
    for (int k = 0; k < 8; k++)
        s1[k] = fmaf(t[2 * k + 1], t[2 * k + 1], t[2 * k] * t[2 * k]);

    float s2[4];
    #pragma unroll
    for (int k = 0; k < 4; k++) s2[k] = s1[2 * k] + s1[2 * k + 1];
    const float s3a = s2[0] + s2[1];
    const float s3b = s2[2] + s2[3];
    const float n   = s3a + s3b;

    const float S0 = s3a;
    const float S1 = s2[0] + s2[2];
    const float S2 = (s1[0] + s1[2]) + (s1[4] + s1[6]);

    // wire 3: lows of the eliminated gate, d_k = lo - t3*hi
    float d0 = fmaf(-t3L2, t[1], t[0]);
    float S3 = d0 * d0;
    #pragma unroll
    for (int k = 1; k < 8; k++) {
        const float dk = fmaf(-t3L2, t[2 * k + 1], t[2 * k]);
        S3 = fmaf(dk, dk, S3);
    }

    const float r2  = 2.0f * frcp_approx(n);
    const float r2j = r2 * j3;
    return make_float4(fmaf(S0, r2, -1.0f), fmaf(S1, r2, -1.0f),
                       fmaf(S2, r2, -1.0f), fmaf(S3, r2j, -1.0f));
}

__global__ __launch_bounds__(256)
void quan2d_kernel(const float* __restrict__ x,
                   const float* __restrict__ w8,
                   float* __restrict__ out)
{
    __shared__ float sh[9];
    const int tid = threadIdx.x;
    if (tid < 8) {
        const float tg = __tanf(0.5f * w8[tid]);
        sh[tid] = tg;
        if (tid == 7) sh[8] = frcp_approx(fmaf(tg, tg, 1.0f));
    }
    __syncthreads();

    float ct[8];
    #pragma unroll
    for (int i = 0; i < 8; i++) ct[i] = sh[i];
    const float t3L2 = ct[7];
    const float j3   = sh[8];

    const int b  = blockIdx.x * 2 + (tid >> 7);   // image
    const int t7 = tid & 127;
    const int pr = t7 >> 3;                        // patch row 0..15
    const int k  = t7 & 7;                         // pair idx; patches pc=2k,2k+1
    const float* base0 = x + (size_t)b * 1024 + (2 * pr) * 32 + 4 * k;

    // --- load 4x6 tile, pre-zeroed, guarded predicated loads only ---
    const bool pA = (pr < 15);
    const bool pB = (k < 7);
    float T[24];
    #pragma unroll
    for (int i = 0; i < 24; i++) T[i] = 0.0f;

    #pragma unroll
    for (int i = 0; i < 4; i++) {
        const float* base = base0 + i * 32;
        const bool rok = (i < 2) || pA;
        float4 F;
        if (rok) {
            F = __ldg((const float4*)base);
            T[6 * i + 0] = F.x; T[6 * i + 1] = F.y;
            T[6 * i + 2] = F.z; T[6 * i + 3] = F.w;
        }
        if (rok && pB) {
            const float2 G = __ldg((const float2*)(base + 4));
            T[6 * i + 4] = G.x; T[6 * i + 5] = G.y;
        }
    }

    // --- shared L1 row gates (wires 0,1) on all 6 tile columns ---
    {
        const float t0 = ct[0], t1 = ct[1];
        #pragma unroll
        for (int c = 0; c < 6; c++) {
            const float x0 = T[c], x1 = T[6 + c], x2 = T[12 + c], x3 = T[18 + c];
            const float y0 = fmaf(-t0, x2, x0);        // wire 0: (r0,r2),(r1,r3)
            const float y2 = fmaf( t0, x0, x2);
            const float y1 = fmaf(-t0, x3, x1);
            const float y3 = fmaf( t0, x1, x3);
            T[c]      = fmaf(-t1, y1, y0);             // wire 1: (r0,r1),(r2,r3)
            T[6 + c]  = fmaf( t1, y0, y1);
            T[12 + c] = fmaf(-t1, y3, y2);
            T[18 + c] = fmaf( t1, y2, y3);
        }
    }

    // --- shared L1 wire-3 col gate: pairs (0,1),(2,3),(4,5) per row ---
    {
        const float t3 = ct[3];
        #pragma unroll
        for (int r = 0; r < 4; r++) {
            #pragma unroll
            for (int p = 0; p < 3; p++) {
                const float lo = T[6 * r + 2 * p], hi = T[6 * r + 2 * p + 1];
                T[6 * r + 2 * p]     = fmaf(-t3, hi, lo);
                T[6 * r + 2 * p + 1] = fmaf( t3, lo, hi);
            }
        }
    }

    const float4 o0 = run_patch(T, 0, ct, t3L2, j3);
    const float4 o1 = run_patch(T, 2, ct, t3L2, j3);

    float4* op = (float4*)out + (size_t)b * 256 + pr * 16 + 2 * k;
    op[0] = o0;
    op[1] = o1;
}

extern "C" void kernel_launch(void* const* d_in, const int* in_sizes, int n_in,
                              void* d_out, int out_size)
{
    const float* x = (const float*)d_in[0];   // [B,1,32,32] fp32
    const float* w = (const float*)d_in[1];   // [1,8] fp32
    const int B = in_sizes[0] / 1024;
    quan2d_kernel<<<B / 2, 256>>>(x, w, (float*)d_out);
}